// round 1
// baseline (speedup 1.0000x reference)
#include <cuda_runtime.h>
#include <cstdint>
#include <cfloat>

// Problem constants: z (2,64,8,64,64), embedding (4096,64)
#define BATCH 2
#define CH 64
#define SPA 32768           // 8*64*64
#define NTOK 65536          // BATCH*SPA
#define KCODE 4096
#define OUT_ELEMS 4194304   // BATCH*CH*SPA
#define KC 128              // codes per smem chunk in main kernel

typedef unsigned long long ull;

// -------- scratch (static device allocations; no cudaMalloc allowed) --------
__device__ float g_tT[CH * NTOK];       // pre-conv output, transposed [c][n], 16MB
__device__ int   g_idx[NTOK];
__device__ float g_e2[KCODE];           // ||e_k||^2
__device__ float g_pe[KCODE * CH];      // embedding @ post_w^T + post_b
__device__ float g_part[256];           // per-block loss partials

// -------- helpers --------
__device__ __forceinline__ ull ffma2(ull a, ull b, ull c) {
    ull d;
    asm("fma.rn.f32x2 %0, %1, %2, %3;" : "=l"(d) : "l"(a), "l"(b), "l"(c));
    return d;
}
__device__ __forceinline__ float f2lo(ull v) { return __uint_as_float((unsigned)v); }
__device__ __forceinline__ float f2hi(ull v) { return __uint_as_float((unsigned)(v >> 32)); }

// ============================================================================
// Kernel P: pe[k][o] = post_b[o] + sum_c emb[k][c]*post_w[o][c];  e2[k] = ||e_k||^2
// grid 256 blocks x 64 threads, 16 codes per block
// ============================================================================
__global__ void kP(const float* __restrict__ emb,
                   const float* __restrict__ post_w,
                   const float* __restrict__ post_b) {
    __shared__ float wsm[64 * 65];   // padded stride 65 -> conflict-free
    __shared__ float esm[64];
    __shared__ float wred[2];
    int tid = threadIdx.x;

    for (int i = tid; i < 4096; i += 64)
        wsm[(i >> 6) * 65 + (i & 63)] = post_w[i];
    float wb = post_b[tid];

    for (int kk = 0; kk < 16; kk++) {
        int k = blockIdx.x * 16 + kk;
        __syncthreads();
        esm[tid] = emb[k * 64 + tid];
        __syncthreads();
        float acc = wb;
#pragma unroll
        for (int c = 0; c < 64; c++)
            acc = fmaf(esm[c], wsm[tid * 65 + c], acc);
        g_pe[k * 64 + tid] = acc;

        float sq = esm[tid] * esm[tid];
#pragma unroll
        for (int off = 16; off; off >>= 1)
            sq += __shfl_xor_sync(0xffffffffu, sq, off);
        if ((tid & 31) == 0) wred[tid >> 5] = sq;
        __syncthreads();
        if (tid == 0) g_e2[k] = wred[0] + wred[1];
    }
}

// ============================================================================
// Kernel A: pre-conv.  tT[o][n] = pre_b[o] + sum_c z[b][c][s]*pre_w[o][c]
// grid 256 x 256, one voxel per thread, z channels in registers
// ============================================================================
__global__ void __launch_bounds__(256) kA(const float* __restrict__ z,
                                          const float* __restrict__ pre_w,
                                          const float* __restrict__ pre_b) {
    __shared__ float wsm[4096];
    __shared__ float bsm[64];
    int tid = threadIdx.x;
    int n = blockIdx.x * 256 + tid;
    for (int i = tid; i < 4096; i += 256) wsm[i] = pre_w[i];
    if (tid < 64) bsm[tid] = pre_b[tid];

    int b = n >> 15;
    int s = n & 32767;
    const float* zp = z + (size_t)b * (CH * SPA) + s;
    float zr[64];
#pragma unroll
    for (int c = 0; c < 64; c++) zr[c] = zp[(size_t)c * SPA];
    __syncthreads();

    for (int o = 0; o < 64; o++) {
        float acc = bsm[o];
#pragma unroll
        for (int c = 0; c < 64; c++)
            acc = fmaf(zr[c], wsm[o * 64 + c], acc);
        g_tT[(size_t)o * NTOK + n] = acc;
    }
}

// ============================================================================
// Kernel B: nearest-code search.  argmin_k ( ||e_k||^2 - 2 t.e_k )
// 2 tokens per thread packed in f32x2; embedding chunk staged in SMEM
// pre-duplicated as {e,e} 8B pairs.  grid 128 x 256.
// ============================================================================
__global__ void __launch_bounds__(256, 1) kB(const float* __restrict__ emb) {
    extern __shared__ ull sh[];                 // KC*64 duplicated pairs
    float* e2s = (float*)(sh + KC * 64);        // KC scalar e2

    int tid = threadIdx.x;
    int n0 = (blockIdx.x * 256 + tid) * 2;

    // load 2 tokens' t as packed pairs: low = token n0, high = token n0+1
    ull t2[64];
#pragma unroll
    for (int c = 0; c < 64; c++)
        t2[c] = *(const ull*)&g_tT[(size_t)c * NTOK + n0];

    float best0 = FLT_MAX, best1 = FLT_MAX;
    int bi0 = 0, bi1 = 0;

    for (int ch = 0; ch < KCODE; ch += KC) {
        __syncthreads();
        const float* eb = emb + (size_t)ch * 64;
        for (int i = tid; i < KC * 64; i += 256) {
            unsigned u = __float_as_uint(eb[i]);
            sh[i] = ((ull)u << 32) | u;         // duplicate into both f32x2 lanes
        }
        if (tid < KC) e2s[tid] = g_e2[ch + tid];
        __syncthreads();

        for (int kk = 0; kk < KC; kk += 2) {
            ull accA = 0, accB = 0;             // {0.f, 0.f}
            const ull* pa = sh + kk * 64;
            const ull* pb = pa + 64;
#pragma unroll
            for (int c = 0; c < 64; c += 2) {
                ulonglong2 ea = *(const ulonglong2*)(pa + c);   // LDS.128 broadcast
                ulonglong2 eb2 = *(const ulonglong2*)(pb + c);
                accA = ffma2(t2[c],     ea.x,  accA);
                accB = ffma2(t2[c],     eb2.x, accB);
                accA = ffma2(t2[c + 1], ea.y,  accA);
                accB = ffma2(t2[c + 1], eb2.y, accB);
            }
            float e2a = e2s[kk], e2b = e2s[kk + 1];
            float sA0 = fmaf(f2lo(accA), -2.0f, e2a);
            float sA1 = fmaf(f2hi(accA), -2.0f, e2a);
            float sB0 = fmaf(f2lo(accB), -2.0f, e2b);
            float sB1 = fmaf(f2hi(accB), -2.0f, e2b);
            // ascending k with strict < matches jnp.argmin first-min tie-break
            if (sA0 < best0) { best0 = sA0; bi0 = ch + kk; }
            if (sB0 < best0) { best0 = sB0; bi0 = ch + kk + 1; }
            if (sA1 < best1) { best1 = sA1; bi1 = ch + kk; }
            if (sB1 < best1) { best1 = sB1; bi1 = ch + kk + 1; }
        }
    }
    g_idx[n0]     = bi0;
    g_idx[n0 + 1] = bi1;
}

// ============================================================================
// Kernel C: gather + loss partials + post-conv (as pe gather) + index output
// grid 256 x 256, one token per thread
// ============================================================================
__global__ void __launch_bounds__(256) kC(const float* __restrict__ emb,
                                          float* __restrict__ dout) {
    int tid = threadIdx.x;
    int n = blockIdx.x * 256 + tid;
    int idx = g_idx[n];

    // loss: sum_c (e_c - t_c)^2
    const float4* er4 = (const float4*)(emb + (size_t)idx * 64);
    float lsum = 0.0f;
#pragma unroll
    for (int c4 = 0; c4 < 16; c4++) {
        float4 e4 = er4[c4];
        int c = c4 * 4;
        float d0 = e4.x - g_tT[(size_t)(c + 0) * NTOK + n];
        float d1 = e4.y - g_tT[(size_t)(c + 1) * NTOK + n];
        float d2 = e4.z - g_tT[(size_t)(c + 2) * NTOK + n];
        float d3 = e4.w - g_tT[(size_t)(c + 3) * NTOK + n];
        lsum = fmaf(d0, d0, lsum);
        lsum = fmaf(d1, d1, lsum);
        lsum = fmaf(d2, d2, lsum);
        lsum = fmaf(d3, d3, lsum);
    }

    // post-conv output = pe[idx] gathered, written to (b, o, s) layout
    int b = n >> 15;
    int s = n & 32767;
    float* op = dout + (size_t)b * (CH * SPA) + s;
    const float4* pr4 = (const float4*)(g_pe + (size_t)idx * 64);
#pragma unroll
    for (int o4 = 0; o4 < 16; o4++) {
        float4 p = pr4[o4];
        int o = o4 * 4;
        op[(size_t)(o + 0) * SPA] = p.x;
        op[(size_t)(o + 1) * SPA] = p.y;
        op[(size_t)(o + 2) * SPA] = p.z;
        op[(size_t)(o + 3) * SPA] = p.w;
    }

    // indices output (as float, after out + 2 loss scalars)
    dout[OUT_ELEMS + 2 + n] = (float)idx;

    // deterministic block reduction of loss
    __shared__ float red[256];
    red[tid] = lsum;
    __syncthreads();
#pragma unroll
    for (int st = 128; st > 0; st >>= 1) {
        if (tid < st) red[tid] += red[tid + st];
        __syncthreads();
    }
    if (tid == 0) g_part[blockIdx.x] = red[0];
}

// ============================================================================
// Kernel D: final deterministic loss reduction -> two identical scalars
// ============================================================================
__global__ void kD(float* __restrict__ dout) {
    __shared__ float red[256];
    int tid = threadIdx.x;
    red[tid] = g_part[tid];
    __syncthreads();
#pragma unroll
    for (int st = 128; st > 0; st >>= 1) {
        if (tid < st) red[tid] += red[tid + st];
        __syncthreads();
    }
    if (tid == 0) {
        float m = red[0] / (float)OUT_ELEMS;   // mean over N*C = 4194304
        dout[OUT_ELEMS]     = m;               // codebook_loss
        dout[OUT_ELEMS + 1] = m;               // commitment_loss (same forward value)
    }
}

// ============================================================================
extern "C" void kernel_launch(void* const* d_in, const int* in_sizes, int n_in,
                              void* d_out, int out_size) {
    const float* z      = (const float*)d_in[0];
    const float* emb    = (const float*)d_in[1];
    const float* pre_w  = (const float*)d_in[2];
    const float* pre_b  = (const float*)d_in[3];
    const float* post_w = (const float*)d_in[4];
    const float* post_b = (const float*)d_in[5];
    float* dout = (float*)d_out;

    static const size_t shbytes = KC * 64 * sizeof(ull) + KC * sizeof(float); // 66048
    cudaFuncSetAttribute(kB, cudaFuncAttributeMaxDynamicSharedMemorySize, (int)shbytes);

    kP<<<KCODE / 16, 64>>>(emb, post_w, post_b);
    kA<<<NTOK / 256, 256>>>(z, pre_w, pre_b);
    kB<<<NTOK / 512, 256, shbytes>>>(emb);
    kC<<<NTOK / 256, 256>>>(emb, dout);
    kD<<<1, 256>>>(dout);
}

// round 2
// speedup vs baseline: 1.3669x; 1.3669x over previous
#include <cuda_runtime.h>
#include <cstdint>
#include <cfloat>

// Problem constants: z (2,64,8,64,64), embedding (4096,64)
#define BATCH 2
#define CH 64
#define SPA 32768           // 8*64*64
#define NTOK 65536          // BATCH*SPA
#define KCODE 4096
#define OUT_ELEMS 4194304   // BATCH*CH*SPA
#define KC 128              // codes per smem chunk in kB
#define EPAD 132            // padded row stride (floats) for esm, 16B-aligned, conflict-light
#define TBLK 64             // tokens per block in kB

typedef unsigned long long ull;

// -------- scratch (static device arrays; no cudaMalloc allowed) --------
__device__ float g_tT[CH * NTOK];       // pre-conv output, transposed [c][n], 16MB
__device__ int   g_idx[NTOK];
__device__ float g_e2[KCODE];           // ||e_k||^2
__device__ float g_pe[KCODE * CH];      // embedding @ post_w^T + post_b
__device__ float g_part[256];           // per-block loss partials

// -------- helpers --------
__device__ __forceinline__ ull ffma2(ull a, ull b, ull c) {
    ull d;
    asm("fma.rn.f32x2 %0, %1, %2, %3;" : "=l"(d) : "l"(a), "l"(b), "l"(c));
    return d;
}
__device__ __forceinline__ ull dup2(float x) {
    ull d;
    unsigned u = __float_as_uint(x);
    asm("mov.b64 %0, {%1, %2};" : "=l"(d) : "r"(u), "r"(u));
    return d;
}
__device__ __forceinline__ float f2lo(ull v) { return __uint_as_float((unsigned)v); }
__device__ __forceinline__ float f2hi(ull v) { return __uint_as_float((unsigned)(v >> 32)); }

// ============================================================================
// Kernel P: pe[k][o] = post_b[o] + sum_c emb[k][c]*post_w[o][c];  e2[k] = ||e_k||^2
// ============================================================================
__global__ void kP(const float* __restrict__ emb,
                   const float* __restrict__ post_w,
                   const float* __restrict__ post_b) {
    __shared__ float wsm[64 * 65];
    __shared__ float esm[64];
    __shared__ float wred[2];
    int tid = threadIdx.x;

    for (int i = tid; i < 4096; i += 64)
        wsm[(i >> 6) * 65 + (i & 63)] = post_w[i];
    float wb = post_b[tid];

    for (int kk = 0; kk < 16; kk++) {
        int k = blockIdx.x * 16 + kk;
        __syncthreads();
        esm[tid] = emb[k * 64 + tid];
        __syncthreads();
        float acc = wb;
#pragma unroll
        for (int c = 0; c < 64; c++)
            acc = fmaf(esm[c], wsm[tid * 65 + c], acc);
        g_pe[k * 64 + tid] = acc;

        float sq = esm[tid] * esm[tid];
#pragma unroll
        for (int off = 16; off; off >>= 1)
            sq += __shfl_xor_sync(0xffffffffu, sq, off);
        if ((tid & 31) == 0) wred[tid >> 5] = sq;
        __syncthreads();
        if (tid == 0) g_e2[k] = wred[0] + wred[1];
    }
}

// ============================================================================
// Kernel A: pre-conv.  tT[o][n] = pre_b[o] + sum_c z[b][c][s]*pre_w[o][c]
// ============================================================================
__global__ void __launch_bounds__(256) kA(const float* __restrict__ z,
                                          const float* __restrict__ pre_w,
                                          const float* __restrict__ pre_b) {
    __shared__ float wsm[4096];
    __shared__ float bsm[64];
    int tid = threadIdx.x;
    int n = blockIdx.x * 256 + tid;
    for (int i = tid; i < 4096; i += 256) wsm[i] = pre_w[i];
    if (tid < 64) bsm[tid] = pre_b[tid];

    int b = n >> 15;
    int s = n & 32767;
    const float* zp = z + (size_t)b * (CH * SPA) + s;
    float zr[64];
#pragma unroll
    for (int c = 0; c < 64; c++) zr[c] = zp[(size_t)c * SPA];
    __syncthreads();

    for (int o = 0; o < 64; o++) {
        float acc = bsm[o];
#pragma unroll
        for (int c = 0; c < 64; c++)
            acc = fmaf(zr[c], wsm[o * 64 + c], acc);
        g_tT[(size_t)o * NTOK + n] = acc;
    }
}

// ============================================================================
// Kernel B v2: nearest-code search, register-tiled.
//   argmin_k ( ||e_k||^2 - 2 t.e_k )
// Block: 64 tokens x 4096 codes (chunks of KC=128 in smem, channel-major).
// Thread (tx=tid&31, ty=tid>>5): 2 tokens x 16 codes, f32x2-packed over code
// pairs. One LDS.128 on esm row delivers 4 codes = 2 ffma2 operand pairs.
// Per channel: 4 LDS.128 (e) + 1 LDS.64 (t) + 2 dups + 16 FFMA2.
// ============================================================================
__global__ void __launch_bounds__(256) kB(const float* __restrict__ emb) {
    extern __shared__ float sm[];
    float* esm = sm;                       // [64][EPAD]
    float* tsm = sm + 64 * EPAD;           // [64][TBLK]
    float* e2s = tsm + 64 * TBLK;          // [KC]

    int tid = threadIdx.x;
    int tx = tid & 31;
    int ty = tid >> 5;
    int n0 = blockIdx.x * TBLK;

    // stage this block's 64 tokens: tsm[c][t]  (coalesced rows of g_tT)
    for (int i = tid; i < 64 * TBLK; i += 256) {
        int c = i >> 6;
        int t = i & (TBLK - 1);
        tsm[c * TBLK + t] = g_tT[(size_t)c * NTOK + n0 + t];
    }

    float best0 = FLT_MAX, best1 = FLT_MAX;
    int bi0 = 0, bi1 = 0;

    for (int chb = 0; chb < KCODE; chb += KC) {
        __syncthreads();
        // load embedding chunk transposed: esm[c][k]  (gmem read coalesced over c)
        const float* eb = emb + (size_t)chb * 64;
        for (int i = tid; i < KC * 64; i += 256) {
            int c = i & 63;
            int k = i >> 6;
            esm[c * EPAD + k] = eb[k * 64 + c];
        }
        if (tid < KC) e2s[tid] = g_e2[chb + tid];
        __syncthreads();

        ull acc[2][8];
#pragma unroll
        for (int t = 0; t < 2; t++)
#pragma unroll
            for (int p = 0; p < 8; p++) acc[t][p] = 0ull;

        const float* erow = esm + ty * 16;
        const float* trow = tsm + tx * 2;
#pragma unroll 8
        for (int c = 0; c < 64; c++) {
            float2 tv = *(const float2*)(trow + c * TBLK);
            ull td0 = dup2(tv.x);
            ull td1 = dup2(tv.y);
            const ulonglong2* ep = (const ulonglong2*)(erow + c * EPAD);
            ulonglong2 e01 = ep[0];   // codes 0..3 of my 16
            ulonglong2 e23 = ep[1];   // codes 4..7
            ulonglong2 e45 = ep[2];   // codes 8..11
            ulonglong2 e67 = ep[3];   // codes 12..15
            acc[0][0] = ffma2(td0, e01.x, acc[0][0]);
            acc[1][0] = ffma2(td1, e01.x, acc[1][0]);
            acc[0][1] = ffma2(td0, e01.y, acc[0][1]);
            acc[1][1] = ffma2(td1, e01.y, acc[1][1]);
            acc[0][2] = ffma2(td0, e23.x, acc[0][2]);
            acc[1][2] = ffma2(td1, e23.x, acc[1][2]);
            acc[0][3] = ffma2(td0, e23.y, acc[0][3]);
            acc[1][3] = ffma2(td1, e23.y, acc[1][3]);
            acc[0][4] = ffma2(td0, e45.x, acc[0][4]);
            acc[1][4] = ffma2(td1, e45.x, acc[1][4]);
            acc[0][5] = ffma2(td0, e45.y, acc[0][5]);
            acc[1][5] = ffma2(td1, e45.y, acc[1][5]);
            acc[0][6] = ffma2(td0, e67.x, acc[0][6]);
            acc[1][6] = ffma2(td1, e67.x, acc[1][6]);
            acc[0][7] = ffma2(td0, e67.y, acc[0][7]);
            acc[1][7] = ffma2(td1, e67.y, acc[1][7]);
        }

        // epilogue: score = e2 - 2*dot ; ascending code order, strict < keeps
        // the lowest index (jnp.argmin tie-break)
        int kb = chb + ty * 16;
#pragma unroll
        for (int p = 0; p < 8; p++) {
            float e2a = e2s[ty * 16 + 2 * p];
            float e2b = e2s[ty * 16 + 2 * p + 1];
            float sA0 = fmaf(f2lo(acc[0][p]), -2.0f, e2a);
            float sB0 = fmaf(f2hi(acc[0][p]), -2.0f, e2b);
            float sA1 = fmaf(f2lo(acc[1][p]), -2.0f, e2a);
            float sB1 = fmaf(f2hi(acc[1][p]), -2.0f, e2b);
            if (sA0 < best0) { best0 = sA0; bi0 = kb + 2 * p; }
            if (sB0 < best0) { best0 = sB0; bi0 = kb + 2 * p + 1; }
            if (sA1 < best1) { best1 = sA1; bi1 = kb + 2 * p; }
            if (sB1 < best1) { best1 = sB1; bi1 = kb + 2 * p + 1; }
        }
    }

    // cross-ty reduction: each token's argmin is split across 8 ty-threads
    __syncthreads();
    float* rbest = sm;                       // [8][TBLK] overlay on esm
    int*   ridx  = (int*)(sm + 8 * TBLK);    // [8][TBLK]
    rbest[ty * TBLK + tx * 2]     = best0;
    rbest[ty * TBLK + tx * 2 + 1] = best1;
    ridx[ty * TBLK + tx * 2]      = bi0;
    ridx[ty * TBLK + tx * 2 + 1]  = bi1;
    __syncthreads();
    if (tid < TBLK) {
        float b = FLT_MAX;
        int bi = 0x7fffffff;
#pragma unroll
        for (int y = 0; y < 8; y++) {
            float v = rbest[y * TBLK + tid];
            int   id = ridx[y * TBLK + tid];
            if (v < b || (v == b && id < bi)) { b = v; bi = id; }
        }
        g_idx[n0 + tid] = bi;
    }
}

// ============================================================================
// Kernel C: loss partials + post-conv (pe gather) + index output
// ============================================================================
__global__ void __launch_bounds__(256) kC(const float* __restrict__ emb,
                                          float* __restrict__ dout) {
    int tid = threadIdx.x;
    int n = blockIdx.x * 256 + tid;
    int idx = g_idx[n];

    const float4* er4 = (const float4*)(emb + (size_t)idx * 64);
    float lsum = 0.0f;
#pragma unroll
    for (int c4 = 0; c4 < 16; c4++) {
        float4 e4 = er4[c4];
        int c = c4 * 4;
        float d0 = e4.x - g_tT[(size_t)(c + 0) * NTOK + n];
        float d1 = e4.y - g_tT[(size_t)(c + 1) * NTOK + n];
        float d2 = e4.z - g_tT[(size_t)(c + 2) * NTOK + n];
        float d3 = e4.w - g_tT[(size_t)(c + 3) * NTOK + n];
        lsum = fmaf(d0, d0, lsum);
        lsum = fmaf(d1, d1, lsum);
        lsum = fmaf(d2, d2, lsum);
        lsum = fmaf(d3, d3, lsum);
    }

    int b = n >> 15;
    int s = n & 32767;
    float* op = dout + (size_t)b * (CH * SPA) + s;
    const float4* pr4 = (const float4*)(g_pe + (size_t)idx * 64);
#pragma unroll
    for (int o4 = 0; o4 < 16; o4++) {
        float4 p = pr4[o4];
        int o = o4 * 4;
        op[(size_t)(o + 0) * SPA] = p.x;
        op[(size_t)(o + 1) * SPA] = p.y;
        op[(size_t)(o + 2) * SPA] = p.z;
        op[(size_t)(o + 3) * SPA] = p.w;
    }

    dout[OUT_ELEMS + 2 + n] = (float)idx;

    __shared__ float red[256];
    red[tid] = lsum;
    __syncthreads();
#pragma unroll
    for (int st = 128; st > 0; st >>= 1) {
        if (tid < st) red[tid] += red[tid + st];
        __syncthreads();
    }
    if (tid == 0) g_part[blockIdx.x] = red[0];
}

// ============================================================================
// Kernel D: final deterministic loss reduction
// ============================================================================
__global__ void kD(float* __restrict__ dout) {
    __shared__ float red[256];
    int tid = threadIdx.x;
    red[tid] = g_part[tid];
    __syncthreads();
#pragma unroll
    for (int st = 128; st > 0; st >>= 1) {
        if (tid < st) red[tid] += red[tid + st];
        __syncthreads();
    }
    if (tid == 0) {
        float m = red[0] / (float)OUT_ELEMS;
        dout[OUT_ELEMS]     = m;   // codebook_loss
        dout[OUT_ELEMS + 1] = m;   // commitment_loss (same forward value)
    }
}

// ============================================================================
extern "C" void kernel_launch(void* const* d_in, const int* in_sizes, int n_in,
                              void* d_out, int out_size) {
    const float* z      = (const float*)d_in[0];
    const float* emb    = (const float*)d_in[1];
    const float* pre_w  = (const float*)d_in[2];
    const float* pre_b  = (const float*)d_in[3];
    const float* post_w = (const float*)d_in[4];
    const float* post_b = (const float*)d_in[5];
    float* dout = (float*)d_out;

    const int shbytes = (64 * EPAD + 64 * TBLK + KC) * sizeof(float);  // 50688
    cudaFuncSetAttribute(kB, cudaFuncAttributeMaxDynamicSharedMemorySize, shbytes);

    kP<<<KCODE / 16, 64>>>(emb, post_w, post_b);
    kA<<<NTOK / 256, 256>>>(z, pre_w, pre_b);
    kB<<<NTOK / TBLK, 256, shbytes>>>(emb);
    kC<<<NTOK / 256, 256>>>(emb, dout);
    kD<<<1, 256>>>(dout);
}